// round 8
// baseline (speedup 1.0000x reference)
#include <cuda_runtime.h>

#define HW   16384
#define NB   2
#define CIN  128
#define CO   64
#define NK   64
#define NPIX (NB*HW)
#define GRIDN 129u
#define NT    512

// accumulator pack
#define ACC_SUMS  0        // 8192 floats: [b][k][o]
#define ACC_CNT   8192     // 128 floats:  [b][k]
#define ACC_BNSUM 8320     // 64
#define ACC_BNSQ  8384     // 64
#define ACCN      8448

// ---------------- scratch (static device globals; zero-initialized by loader) ----------------
__device__ float    g_xt[(size_t)NPIX*CO];   // [b][hw][o] pixel-major, 8 MB
__device__ float    g_acc[ACCN];
__device__ unsigned g_bar;                   // monotonic ticket barrier
__device__ float    g_invcov[CO*CO];
__device__ float    g_means[NB*NK*CO];
__device__ float    g_T[NB*NK*CO];
__device__ float    g_diag[NB*NK];
__device__ float    g_adjm[NB*NK*CO];

// ---------------- helpers ----------------
__device__ __forceinline__ unsigned long long pk2(float v) {
    unsigned long long r; unsigned u = __float_as_uint(v);
    asm("mov.b64 %0, {%1, %2};" : "=l"(r) : "r"(u), "r"(u));
    return r;
}
__device__ __forceinline__ void ffma2(unsigned long long& d,
                                      unsigned long long a, unsigned long long b) {
    asm("fma.rn.f32x2 %0, %1, %2, %3;" : "=l"(d) : "l"(a), "l"(b), "l"(d));
}
__device__ __forceinline__ void red4(float* p, float a, float b, float c, float d) {
    asm volatile("red.add.v4.f32 [%0], {%1, %2, %3, %4};"
                 :: "l"(p), "f"(a), "f"(b), "f"(c), "f"(d) : "memory");
}
__device__ __forceinline__ void cpa16(float* sdst, const float* gsrc) {
    unsigned saddr = (unsigned)__cvta_generic_to_shared(sdst);
    asm volatile("cp.async.ca.shared.global [%0], [%1], 16;" :: "r"(saddr), "l"(gsrc));
}
__device__ __forceinline__ void cpa_commit() { asm volatile("cp.async.commit_group;"); }
template<int N> __device__ __forceinline__ void cpa_wait() {
    asm volatile("cp.async.wait_group %0;" :: "n"(N));
}

// device-wide ticket barrier; all GRIDN blocks resident, monotonic across replays
__device__ __forceinline__ void gbar() {
    __threadfence();
    __syncthreads();
    if (threadIdx.x == 0) {
        unsigned t   = atomicAdd(&g_bar, 1u);
        unsigned tgt = (t / GRIDN + 1u) * GRIDN;
        unsigned v;
        for (;;) {
            asm volatile("ld.acquire.gpu.u32 %0, [%1];" : "=r"(v) : "l"(&g_bar) : "memory");
            if (v >= tgt) break;
            __nanosleep(32);
        }
    }
    __syncthreads();
}

// smem union (floats): GEMM: xs[4x2048] | ws[4x512] | scnt[64] | sidxP[256 ints]
#define SMN 10560

// ---------------- the single fused kernel ----------------
__global__ __launch_bounds__(NT) void k_all(const float* __restrict__ x,
                                            const float* __restrict__ Wft,
                                            const int*   __restrict__ idx,
                                            const float* __restrict__ Wm,
                                            float* __restrict__ out,
                                            const float* __restrict__ gamma,
                                            const float* __restrict__ beta) {
    __shared__ float sm[SMN];                  // 41.25 KB union
    int* sidxP = (int*)(sm + 10304);           // persistent across P0/P3/P4
    const int tid = threadIdx.x;
    const int bx  = blockIdx.x;

    const int P0  = bx * 256;                  // pixel tile for blocks 0..127
    const int b   = P0 >> 14;
    const int hw0 = P0 & (HW-1);

    // ================= P0: GEMM (0..127) | inverse (128) =================
    if (bx == 128) {
        if (tid < 128) g_acc[ACC_BNSUM + tid] = 0.f;
        float* aug  = sm;            // 64 x 128
        float* colp = sm + 8192;     // 64
        float* prow = sm + 8256;     // 128
        for (int e = tid; e < 4096; e += NT) {
            int i = e >> 6, j = e & 63;
            float s = 0.f;
            for (int c = 0; c < 64; c += 4) {
                float4 a  = *(const float4*)(Wm + i*64 + c);
                float4 bb = *(const float4*)(Wm + j*64 + c);
                s += a.x*bb.x + a.y*bb.y + a.z*bb.z + a.w*bb.w;
            }
            aug[i*128 + j]      = s;
            aug[i*128 + 64 + j] = (i == j) ? 1.f : 0.f;
        }
        __syncthreads();
        for (int p = 0; p < 64; p++) {
            if (tid < 64) {
                colp[tid] = aug[tid*128 + p];
            } else if (tid < 192) {
                int j = tid - 64;
                prow[j] = aug[p*128 + j] * (1.f / aug[p*128 + p]);
            }
            __syncthreads();
            for (int e = tid; e < 8192; e += NT) {
                int i = e >> 7, j = e & 127;
                float pr = prow[j];
                aug[e] = (i == p) ? pr : fmaf(-colp[i], pr, aug[e]);
            }
            __syncthreads();
        }
        for (int e = tid; e < 4096; e += NT)
            g_invcov[e] = aug[(e>>6)*128 + 64 + (e&63)];
    } else {
        // ---- GEMM: 256 px x 64 out, 4-stage cp.async ring, 1 barrier/iter ----
        float* xs   = sm;            // 4 x 2048  (8 ch x 256 px per stage)
        float* ws   = sm + 8192;     // 4 x 512   (8 ch x 64 o per stage)
        float* scnt = sm + 10240;    // 64

        const float* xb = x + (size_t)b*CIN*HW + hw0;

        if (tid < 64) {
            scnt[tid] = 0.f;
            ((int4*)sidxP)[tid] = ((const int4*)(idx + P0))[tid];
        }

        const int chg = tid & 7;     // 8 o-groups of 8
        const int pxq = tid >> 3;    // 64 px-groups of 4
        unsigned long long acc2[4][4];
#pragma unroll
        for (int i = 0; i < 4; i++)
#pragma unroll
            for (int j = 0; j < 4; j++) acc2[i][j] = 0ull;

        const int xr = tid >> 6, xc = (tid & 63) * 4;   // 8 rows x 256 px: 1 cpa16/thread
        // prologue: prefetch tiles 0..2
#pragma unroll
        for (int pt = 0; pt < 3; pt++) {
            cpa16(xs + pt*2048 + xr*256 + xc, xb + (size_t)(pt*8 + xr)*HW + xc);
            if (tid < 128) cpa16(ws + pt*512 + tid*4, Wft + (size_t)pt*8*CO + tid*4);
            cpa_commit();
        }

        for (int t = 0; t < 16; t++) {                  // 16 tiles of 8 channels
            cpa_wait<2>();          // FIFO: tile t's group has landed
            __syncthreads();        // all warps done with compute t-1 + their waits
            if (t < 13) {
                const int pt  = t + 3;
                const int pb  = pt & 3;                 // = (t-1)&3, safe after sync
                cpa16(xs + pb*2048 + xr*256 + xc, xb + (size_t)(pt*8 + xr)*HW + xc);
                if (tid < 128) cpa16(ws + pb*512 + tid*4, Wft + (size_t)pt*8*CO + tid*4);
            }
            cpa_commit();           // one group per iter (possibly empty) keeps FIFO math fixed
            const int buf = t & 3;
            const float* xsb = xs + buf*2048;
            const float* wsb = ws + buf*512;
#pragma unroll
            for (int cc = 0; cc < 8; cc++) {
                float xv[4];
                *(float4*)xv = *(const float4*)(xsb + cc*256 + pxq*4);
                ulonglong2 wA = *(const ulonglong2*)(wsb + cc*64 + chg*8);
                ulonglong2 wB = *(const ulonglong2*)(wsb + cc*64 + chg*8 + 4);
#pragma unroll
                for (int i = 0; i < 4; i++) {
                    unsigned long long ax = pk2(xv[i]);
                    ffma2(acc2[i][0], ax, wA.x);
                    ffma2(acc2[i][1], ax, wA.y);
                    ffma2(acc2[i][2], ax, wB.x);
                    ffma2(acc2[i][3], ax, wB.y);
                }
            }
        }

        float* ob = g_xt + ((size_t)b*HW + hw0)*CO;
#pragma unroll
        for (int i = 0; i < 4; i++) {
            int px = pxq*4 + i;
            unsigned long long a0 = acc2[i][0], a1 = acc2[i][1],
                               a2 = acc2[i][2], a3 = acc2[i][3];
            float v0 = __uint_as_float((unsigned)a0), v1 = __uint_as_float((unsigned)(a0>>32));
            float v2 = __uint_as_float((unsigned)a1), v3 = __uint_as_float((unsigned)(a1>>32));
            float v4 = __uint_as_float((unsigned)a2), v5 = __uint_as_float((unsigned)(a2>>32));
            float v6 = __uint_as_float((unsigned)a3), v7 = __uint_as_float((unsigned)(a3>>32));
            *(float4*)(ob + (size_t)px*CO + chg*8)     = make_float4(v0,v1,v2,v3);
            *(float4*)(ob + (size_t)px*CO + chg*8 + 4) = make_float4(v4,v5,v6,v7);
            int k = sidxP[px];
            float* sp = g_acc + ACC_SUMS + ((b*NK + k)*CO + chg*8);
            red4(sp,     v0,v1,v2,v3);
            red4(sp + 4, v4,v5,v6,v7);
            if (chg == 0) atomicAdd(&scnt[k], 1.f);
        }
        __syncthreads();
        if (tid < 64) atomicAdd(&g_acc[ACC_CNT + b*64 + tid], scnt[tid]);
    }
    gbar();

    // ================= P1: adjA (blocks 0..15) =================
    if (bx < 16) {
        float* As = sm;            // 4096
        float* mR = sm + 4096;     // 512
        float* tR = sm + 4608;     // 512
        const int ab = bx >> 3, r0 = (bx & 7) * 8;
        for (int e4 = tid; e4 < 1024; e4 += NT)
            ((float4*)As)[e4] = ((const float4*)g_invcov)[e4];
        for (int e = tid; e < 512; e += NT) {
            int rl = e >> 6;
            float c = g_acc[ACC_CNT + ab*64 + r0 + rl];
            float v = g_acc[ACC_SUMS + ab*4096 + r0*64 + e] / ((c > 0.f) ? c : 1.f);
            mR[e] = v;
            g_means[ab*4096 + r0*64 + e] = v;
        }
        __syncthreads();
        {
            int il = tid >> 6, j = tid & 63;          // one (row, col) per thread
            float a = 0.f;
            for (int c = 0; c < 64; c++)
                a = fmaf(mR[il*64 + c], As[c*64 + j], a);
            tR[il*64 + j] = a;
            g_T[ab*4096 + (r0+il)*64 + j] = a;
        }
        __syncthreads();
        if (tid < 8) {
            float d = 0.f;
            for (int c = 0; c < 64; c++)
                d = fmaf(tR[tid*64 + c], mR[tid*64 + c], d);
            g_diag[ab*64 + r0 + tid] = d;
        }
    }
    gbar();

    // ================= P2: adjB (blocks 0..15) =================
    if (bx < 16) {
        float* Ms   = sm;          // 4096 swizzled means [c*64 + (j^(c&31))]
        float* tRb  = sm + 4096;   // 512
        float* sadj = sm + 4608;   // 512
        float* dg   = sm + 5120;   // 64
        const int ab = bx >> 3, r0 = (bx & 7) * 8;
        for (int e = tid; e < 4096; e += NT) {
            int j = e >> 6, c = e & 63;
            Ms[c*64 + (j ^ (c & 31))] = g_means[ab*4096 + e];
        }
        for (int e = tid; e < 512; e += NT)
            tRb[e] = g_T[ab*4096 + r0*64 + e];
        if (tid < 64) dg[tid] = g_diag[ab*64 + tid];
        __syncthreads();
        {
            int il = tid >> 6, j = tid & 63;
            float a = 0.f;
            for (int c = 0; c < 64; c++)
                a = fmaf(tRb[il*64 + c], Ms[c*64 + (j ^ (c & 31))], a);
            float q = dg[r0+il] + dg[j] - 2.f*a;
            sadj[il*64 + j] = expf(-sqrtf(fmaxf(q, 1e-12f)));
        }
        __syncthreads();
        {
            int il = tid >> 6, o = tid & 63;
            float a = 0.f;
            for (int jj = 0; jj < 64; jj++)
                a = fmaf(sadj[il*64 + jj], Ms[o*64 + (jj ^ (o & 31))], a);
            g_adjm[ab*4096 + (r0+il)*64 + o] = a;
        }
    }
    gbar();

    // ================= P3: BN stats (blocks 0..127) + re-zero SUMS/CNT =================
    if (bx < 128) {
        float* am4 = sm;           // 4096
        float* red = sm + 4096;    // 4096: s partials [2048] + q partials [2048]
        for (int e4 = tid; e4 < 1024; e4 += NT)
            ((float4*)am4)[e4] = ((const float4*)(g_adjm + b*4096))[e4];
        if (tid < 65) g_acc[bx*65 + tid] = 0.f;     // 128*65 = 8320 = SUMS+CNT
        __syncthreads();

        const int pr = tid >> 4, c4 = tid & 15;     // 32 px-rows x 16 ch-chunks
        const float4* xb4 = (const float4*)(g_xt + (size_t)P0*CO);
        float4 s4 = make_float4(0,0,0,0), q4 = make_float4(0,0,0,0);
#pragma unroll
        for (int it = 0; it < 8; it++) {
            int px = it*32 + pr;
            int k  = sidxP[px];
            float4 xv = xb4[px*16 + c4];
            float4 av = ((float4*)am4)[k*16 + c4];
            float v0 = fmaxf(xv.x+av.x, 0.f), v1 = fmaxf(xv.y+av.y, 0.f);
            float v2 = fmaxf(xv.z+av.z, 0.f), v3 = fmaxf(xv.w+av.w, 0.f);
            s4.x += v0; s4.y += v1; s4.z += v2; s4.w += v3;
            q4.x += v0*v0; q4.y += v1*v1; q4.z += v2*v2; q4.w += v3*v3;
        }
        ((float4*)red)[pr*16 + c4] = s4;
        ((float4*)(red + 2048))[pr*16 + c4] = q4;
        __syncthreads();
        if (tid < 64) {
            float s = 0.f, q = 0.f;
#pragma unroll
            for (int p = 0; p < 32; p++) { s += red[p*64 + tid]; q += red[2048 + p*64 + tid]; }
            atomicAdd(&g_acc[ACC_BNSUM + tid], s);
            atomicAdd(&g_acc[ACC_BNSQ  + tid], q);
        }
    }
    gbar();

    // ================= P4: finalize (blocks 0..127) =================
    if (bx < 128) {
        float* ams = sm;           // 4096  [k][o ^ (k&31)]
        float* xts = sm + 4096;    // 2112  [o][px] padded 33
        float* ssc = sm + 6208;    // 64
        float* sbi = sm + 6272;    // 64
        for (int e4 = tid; e4 < 1024; e4 += NT) {
            float4 v = ((const float4*)(g_adjm + b*4096))[e4];
            int flat = e4*4, k = flat >> 6, o = flat & 63, sw = k & 31;
            ams[k*64 + ((o+0)^sw)] = v.x;
            ams[k*64 + ((o+1)^sw)] = v.y;
            ams[k*64 + ((o+2)^sw)] = v.z;
            ams[k*64 + ((o+3)^sw)] = v.w;
        }
        if (tid < 64) {
            const float invN = 1.f/(float)NPIX;
            float mean = __ldcg(&g_acc[ACC_BNSUM + tid])*invN;
            float var  = __ldcg(&g_acc[ACC_BNSQ  + tid])*invN - mean*mean;
            float s = gamma[tid]*rsqrtf(var + 1e-5f);
            ssc[tid] = s; sbi[tid] = beta[tid] - mean*s;
        }
        __syncthreads();

        const int w = tid >> 5, lane = tid & 31;    // 16 warps x 4 o each
        float sc4[4], bi4[4];
#pragma unroll
        for (int oo = 0; oo < 4; oo++) { sc4[oo] = ssc[w*4+oo]; bi4[oo] = sbi[w*4+oo]; }

        for (int st = 0; st < 8; st++) {            // 8 subtiles of 32 px
            __syncthreads();
            const float* xbs = g_xt + (size_t)(P0 + st*32)*CO;
            for (int e4 = tid; e4 < 512; e4 += NT) {
                float4 v = ((const float4*)xbs)[e4];
                int flat = e4*4, px = flat >> 6, o = flat & 63;
                xts[(o+0)*33 + px] = v.x;
                xts[(o+1)*33 + px] = v.y;
                xts[(o+2)*33 + px] = v.z;
                xts[(o+3)*33 + px] = v.w;
            }
            __syncthreads();
            int px  = lane;
            int k   = sidxP[st*32 + px];
            int ksw = k & 31;
            float* ob = out + (size_t)b*CO*HW + hw0 + st*32;
#pragma unroll
            for (int oo = 0; oo < 4; oo++) {
                int o = w*4 + oo;
                float v = xts[o*33 + px] + ams[k*64 + (o ^ ksw)];
                v = fmaxf(v, 0.f);
                ob[(size_t)o*HW + px] = fmaf(v, sc4[oo], bi4[oo]);
            }
        }
    }
}

// ---------------- launch ----------------
extern "C" void kernel_launch(void* const* d_in, const int* in_sizes, int n_in,
                              void* d_out, int out_size) {
    const float* x     = (const float*)d_in[0];
    const int*   index = (const int*)  d_in[1];
    const float* Wft   = (const float*)d_in[2];
    const float* Wm    = (const float*)d_in[3];
    const float* gamma = (const float*)d_in[4];
    const float* beta  = (const float*)d_in[5];
    float* out = (float*)d_out;

    k_all<<<GRIDN, NT>>>(x, Wft, index, Wm, out, gamma, beta);
}

// round 9
// speedup vs baseline: 1.0789x; 1.0789x over previous
#include <cuda_runtime.h>

#define HW   16384
#define NB   2
#define CIN  128
#define CO   64
#define NK   64
#define NPIX (NB*HW)
#define GRIDN 129u
#define NT    512

// accumulator pack
#define ACC_SUMS  0        // 8192 floats: [b][k][o]
#define ACC_CNT   8192     // 128 floats:  [b][k]
#define ACC_BNSUM 8320     // 64
#define ACC_BNSQ  8384     // 64
#define ACCN      8448

// smem layout (floats)
#define SCNT_OFF  10240
#define SIDX_OFF  10304
#define FEAT_OFF  10560
#define FEAT_STR  68                     // 64 ch + 4 pad per px
#define SMEM_FLOATS (FEAT_OFF + 256*FEAT_STR)   // 27968
#define SMEM_BYTES  (SMEM_FLOATS*4)             // 111872

// ---------------- scratch (static device globals; zero-initialized by loader) ----------------
__device__ float    g_xt[(size_t)NPIX*CO];   // [b][hw][o] pixel-major, 8 MB
__device__ float    g_acc[ACCN];
__device__ unsigned g_bar;                   // monotonic ticket barrier
__device__ float    g_invcov[CO*CO];
__device__ float    g_means[NB*NK*CO];
__device__ float    g_T[NB*NK*CO];
__device__ float    g_diag[NB*NK];
__device__ float    g_adjm[NB*NK*CO];

// ---------------- helpers ----------------
__device__ __forceinline__ unsigned long long pk2(float v) {
    unsigned long long r; unsigned u = __float_as_uint(v);
    asm("mov.b64 %0, {%1, %2};" : "=l"(r) : "r"(u), "r"(u));
    return r;
}
__device__ __forceinline__ void ffma2(unsigned long long& d,
                                      unsigned long long a, unsigned long long b) {
    asm("fma.rn.f32x2 %0, %1, %2, %3;" : "=l"(d) : "l"(a), "l"(b), "l"(d));
}
__device__ __forceinline__ void red4(float* p, float a, float b, float c, float d) {
    asm volatile("red.add.v4.f32 [%0], {%1, %2, %3, %4};"
                 :: "l"(p), "f"(a), "f"(b), "f"(c), "f"(d) : "memory");
}
__device__ __forceinline__ void cpa16(float* sdst, const float* gsrc) {
    unsigned saddr = (unsigned)__cvta_generic_to_shared(sdst);
    asm volatile("cp.async.ca.shared.global [%0], [%1], 16;" :: "r"(saddr), "l"(gsrc));
}
__device__ __forceinline__ void cpa_commit() { asm volatile("cp.async.commit_group;"); }
template<int N> __device__ __forceinline__ void cpa_wait() {
    asm volatile("cp.async.wait_group %0;" :: "n"(N));
}

// device-wide ticket barrier; all GRIDN blocks resident, monotonic across replays
__device__ __forceinline__ void gbar() {
    __threadfence();
    __syncthreads();
    if (threadIdx.x == 0) {
        unsigned t   = atomicAdd(&g_bar, 1u);
        unsigned tgt = (t / GRIDN + 1u) * GRIDN;
        unsigned v;
        for (;;) {
            asm volatile("ld.acquire.gpu.u32 %0, [%1];" : "=r"(v) : "l"(&g_bar) : "memory");
            if (v >= tgt) break;
            __nanosleep(32);
        }
    }
    __syncthreads();
}

// ---------------- the single fused kernel ----------------
__global__ __launch_bounds__(NT) void k_all(const float* __restrict__ x,
                                            const float* __restrict__ Wft,
                                            const int*   __restrict__ idx,
                                            const float* __restrict__ Wm,
                                            float* __restrict__ out,
                                            const float* __restrict__ gamma,
                                            const float* __restrict__ beta) {
    extern __shared__ float sm[];
    int*   sidxP = (int*)(sm + SIDX_OFF);
    float* feat  = sm + FEAT_OFF;
    const int tid = threadIdx.x;
    const int bx  = blockIdx.x;

    const int P0  = bx * 256;                  // pixel tile for blocks 0..127
    const int b   = P0 >> 14;
    const int hw0 = P0 & (HW-1);

    // ================= P0: GEMM (0..127) | inverse (128) =================
    if (bx == 128) {
        if (tid < 128) g_acc[ACC_BNSUM + tid] = 0.f;
        float* aug  = sm;            // 64 x 128
        float* colp = sm + 8192;     // 64
        float* prow = sm + 8256;     // 128
        for (int e = tid; e < 4096; e += NT) {
            int i = e >> 6, j = e & 63;
            float s = 0.f;
            for (int c = 0; c < 64; c += 4) {
                float4 a  = *(const float4*)(Wm + i*64 + c);
                float4 bb = *(const float4*)(Wm + j*64 + c);
                s += a.x*bb.x + a.y*bb.y + a.z*bb.z + a.w*bb.w;
            }
            aug[i*128 + j]      = s;
            aug[i*128 + 64 + j] = (i == j) ? 1.f : 0.f;
        }
        __syncthreads();
        for (int p = 0; p < 64; p++) {
            if (tid < 64) {
                colp[tid] = aug[tid*128 + p];
            } else if (tid < 192) {
                int j = tid - 64;
                prow[j] = aug[p*128 + j] * (1.f / aug[p*128 + p]);
            }
            __syncthreads();
            for (int e = tid; e < 8192; e += NT) {
                int i = e >> 7, j = e & 127;
                float pr = prow[j];
                aug[e] = (i == p) ? pr : fmaf(-colp[i], pr, aug[e]);
            }
            __syncthreads();
        }
        for (int e = tid; e < 4096; e += NT)
            g_invcov[e] = aug[(e>>6)*128 + 64 + (e&63)];
    } else {
        // ---- GEMM: 256 px x 64 out, 512 threads, whole-Wft smem, x dbl-buffered (R7) ----
        float* ws   = sm;            // 8192 = full Wft
        float* xs   = sm + 8192;     // 2 x 1024 (4 ch x 256 px)
        float* scnt = sm + SCNT_OFF; // 64

        const float* xb = x + (size_t)b*CIN*HW + hw0;

        if (tid < 64) {
            scnt[tid] = 0.f;
            ((int4*)sidxP)[tid] = ((const int4*)(idx + P0))[tid];
        }

        const int chg = tid & 7;     // 8 o-groups of 8
        const int pxq = tid >> 3;    // 64 px-groups of 4
        unsigned long long acc2[4][4];
#pragma unroll
        for (int i = 0; i < 4; i++)
#pragma unroll
            for (int j = 0; j < 4; j++) acc2[i][j] = 0ull;

        // stage whole Wft + first x tile
        for (int e4 = tid; e4 < 2048; e4 += NT)
            cpa16(ws + e4*4, Wft + e4*4);
        const int xr = tid >> 6, xc = (tid & 63) * 4;   // 256 loaders: 4 rows x 256 px
        if (tid < 256) cpa16(xs + xr*256 + xc, xb + (size_t)xr*HW + xc);
        cpa_commit();

        for (int t = 0; t < 32; t++) {                  // 32 tiles of 4 channels
            const int buf = t & 1;
            if (t < 31) {
                if (tid < 256)
                    cpa16(xs + (buf^1)*1024 + xr*256 + xc,
                          xb + (size_t)((t+1)*4 + xr)*HW + xc);
                cpa_commit();
                cpa_wait<1>();
            } else {
                cpa_wait<0>();
            }
            __syncthreads();
            const float* xsb = xs + buf*1024;
#pragma unroll
            for (int cc = 0; cc < 4; cc++) {
                const float* wrow = ws + (t*4 + cc)*64;
                float xv[4];
                *(float4*)xv = *(const float4*)(xsb + cc*256 + pxq*4);
                ulonglong2 wA = *(const ulonglong2*)(wrow + chg*8);
                ulonglong2 wB = *(const ulonglong2*)(wrow + chg*8 + 4);
#pragma unroll
                for (int i = 0; i < 4; i++) {
                    unsigned long long ax = pk2(xv[i]);
                    ffma2(acc2[i][0], ax, wA.x);
                    ffma2(acc2[i][1], ax, wA.y);
                    ffma2(acc2[i][2], ax, wB.x);
                    ffma2(acc2[i][3], ax, wB.y);
                }
            }
            __syncthreads();
        }

        float* ob = g_xt + ((size_t)b*HW + hw0)*CO;
#pragma unroll
        for (int i = 0; i < 4; i++) {
            int px = pxq*4 + i;
            unsigned long long a0 = acc2[i][0], a1 = acc2[i][1],
                               a2 = acc2[i][2], a3 = acc2[i][3];
            float v0 = __uint_as_float((unsigned)a0), v1 = __uint_as_float((unsigned)(a0>>32));
            float v2 = __uint_as_float((unsigned)a1), v3 = __uint_as_float((unsigned)(a1>>32));
            float v4 = __uint_as_float((unsigned)a2), v5 = __uint_as_float((unsigned)(a2>>32));
            float v6 = __uint_as_float((unsigned)a3), v7 = __uint_as_float((unsigned)(a3>>32));
            *(float4*)(ob + (size_t)px*CO + chg*8)     = make_float4(v0,v1,v2,v3);
            *(float4*)(ob + (size_t)px*CO + chg*8 + 4) = make_float4(v4,v5,v6,v7);
            int k = sidxP[px];
            float* sp = g_acc + ACC_SUMS + ((b*NK + k)*CO + chg*8);
            red4(sp,     v0,v1,v2,v3);
            red4(sp + 4, v4,v5,v6,v7);
            if (chg == 0) atomicAdd(&scnt[k], 1.f);
        }
        __syncthreads();
        if (tid < 64) atomicAdd(&g_acc[ACC_CNT + b*64 + tid], scnt[tid]);
    }
    gbar();

    // ---- prefetch this block's xt tile into smem feat (overlaps P1/P2) ----
    if (bx < 128) {
        const float* xtb = g_xt + (size_t)P0*CO;
        for (int p8 = tid; p8 < 4096; p8 += NT) {       // 256 px x 16 chunks of 16B
            int px = p8 >> 4, c4 = p8 & 15;
            cpa16(feat + px*FEAT_STR + c4*4, xtb + px*64 + c4*4);
        }
        cpa_commit();
    }

    // ================= P1: adjA (blocks 0..15) =================
    if (bx < 16) {
        float* As = sm;            // 4096
        float* mR = sm + 4096;     // 512
        float* tR = sm + 4608;     // 512
        const int ab = bx >> 3, r0 = (bx & 7) * 8;
        for (int e4 = tid; e4 < 1024; e4 += NT)
            ((float4*)As)[e4] = ((const float4*)g_invcov)[e4];
        for (int e = tid; e < 512; e += NT) {
            int rl = e >> 6;
            float c = g_acc[ACC_CNT + ab*64 + r0 + rl];
            float v = g_acc[ACC_SUMS + ab*4096 + r0*64 + e] / ((c > 0.f) ? c : 1.f);
            mR[e] = v;
            g_means[ab*4096 + r0*64 + e] = v;
        }
        __syncthreads();
        {
            int il = tid >> 6, j = tid & 63;          // one (row, col) per thread
            float a = 0.f;
            for (int c = 0; c < 64; c++)
                a = fmaf(mR[il*64 + c], As[c*64 + j], a);
            tR[il*64 + j] = a;
            g_T[ab*4096 + (r0+il)*64 + j] = a;
        }
        __syncthreads();
        if (tid < 8) {
            float d = 0.f;
            for (int c = 0; c < 64; c++)
                d = fmaf(tR[tid*64 + c], mR[tid*64 + c], d);
            g_diag[ab*64 + r0 + tid] = d;
        }
    }
    gbar();

    // ================= P2: adjB (blocks 0..15) =================
    if (bx < 16) {
        float* Ms   = sm;          // 4096 swizzled means [c*64 + (j^(c&31))]
        float* tRb  = sm + 4096;   // 512
        float* sadj = sm + 4608;   // 512
        float* dg   = sm + 5120;   // 64
        const int ab = bx >> 3, r0 = (bx & 7) * 8;
        for (int e = tid; e < 4096; e += NT) {
            int j = e >> 6, c = e & 63;
            Ms[c*64 + (j ^ (c & 31))] = g_means[ab*4096 + e];
        }
        for (int e = tid; e < 512; e += NT)
            tRb[e] = g_T[ab*4096 + r0*64 + e];
        if (tid < 64) dg[tid] = g_diag[ab*64 + tid];
        __syncthreads();
        {
            int il = tid >> 6, j = tid & 63;
            float a = 0.f;
            for (int c = 0; c < 64; c++)
                a = fmaf(tRb[il*64 + c], Ms[c*64 + (j ^ (c & 31))], a);
            float q = dg[r0+il] + dg[j] - 2.f*a;
            sadj[il*64 + j] = expf(-sqrtf(fmaxf(q, 1e-12f)));
        }
        __syncthreads();
        {
            int il = tid >> 6, o = tid & 63;
            float a = 0.f;
            for (int jj = 0; jj < 64; jj++)
                a = fmaf(sadj[il*64 + jj], Ms[o*64 + (jj ^ (o & 31))], a);
            g_adjm[ab*4096 + (r0+il)*64 + o] = a;
        }
    }
    gbar();

    // ================= P3: features in smem + BN stats (blocks 0..127) =================
    if (bx < 128) {
        float* am4 = sm;           // 4096
        float* red = sm + 4096;    // 4096: s partials [2048] + q partials [2048]
        for (int e4 = tid; e4 < 1024; e4 += NT)
            ((float4*)am4)[e4] = ((const float4*)(g_adjm + b*4096))[e4];
        if (tid < 65) g_acc[bx*65 + tid] = 0.f;     // 128*65 = 8320 = SUMS+CNT re-zero
        cpa_wait<0>();                              // own feat chunks landed
        __syncthreads();

        const int pr = tid >> 4, c4 = tid & 15;     // 32 px-rows x 16 ch-chunks
        float4 s4 = make_float4(0,0,0,0), q4 = make_float4(0,0,0,0);
#pragma unroll
        for (int it = 0; it < 8; it++) {
            int px = it*32 + pr;
            int k  = sidxP[px];
            float4* fp = (float4*)(feat + px*FEAT_STR + c4*4);
            float4 xv = *fp;
            float4 av = ((float4*)am4)[k*16 + c4];
            float v0 = fmaxf(xv.x+av.x, 0.f), v1 = fmaxf(xv.y+av.y, 0.f);
            float v2 = fmaxf(xv.z+av.z, 0.f), v3 = fmaxf(xv.w+av.w, 0.f);
            *fp = make_float4(v0, v1, v2, v3);      // features materialized in smem
            s4.x += v0; s4.y += v1; s4.z += v2; s4.w += v3;
            q4.x += v0*v0; q4.y += v1*v1; q4.z += v2*v2; q4.w += v3*v3;
        }
        ((float4*)red)[pr*16 + c4] = s4;
        ((float4*)(red + 2048))[pr*16 + c4] = q4;
        __syncthreads();
        if (tid < 64) {
            float s = 0.f, q = 0.f;
#pragma unroll
            for (int p = 0; p < 32; p++) { s += red[p*64 + tid]; q += red[2048 + p*64 + tid]; }
            atomicAdd(&g_acc[ACC_BNSUM + tid], s);
            atomicAdd(&g_acc[ACC_BNSQ  + tid], q);
        }
    }
    gbar();

    // ================= P4: normalize from smem features, coalesced write =================
    if (bx < 128) {
        float* xts = sm;           // 2112  [o][px] padded 33
        float* ssc = sm + 2112;    // 64
        float* sbi = sm + 2176;    // 64
        if (tid < 64) {
            const float invN = 1.f/(float)NPIX;
            float mean = __ldcg(&g_acc[ACC_BNSUM + tid])*invN;
            float var  = __ldcg(&g_acc[ACC_BNSQ  + tid])*invN - mean*mean;
            float s = gamma[tid]*rsqrtf(var + 1e-5f);
            ssc[tid] = s; sbi[tid] = beta[tid] - mean*s;
        }
        __syncthreads();

        const int w = tid >> 5, lane = tid & 31;    // 16 warps x 4 o each
        float sc4[4], bi4[4];
#pragma unroll
        for (int oo = 0; oo < 4; oo++) { sc4[oo] = ssc[w*4+oo]; bi4[oo] = sbi[w*4+oo]; }

        for (int st = 0; st < 8; st++) {            // 8 subtiles of 32 px
            __syncthreads();
            for (int e4 = tid; e4 < 512; e4 += NT) {
                int flat = e4*4, pxl = flat >> 6, o = flat & 63;
                float4 v = *(const float4*)(feat + (st*32 + pxl)*FEAT_STR + o);
                xts[(o+0)*33 + pxl] = v.x;
                xts[(o+1)*33 + pxl] = v.y;
                xts[(o+2)*33 + pxl] = v.z;
                xts[(o+3)*33 + pxl] = v.w;
            }
            __syncthreads();
            float* ob = out + (size_t)b*CO*HW + hw0 + st*32;
#pragma unroll
            for (int oo = 0; oo < 4; oo++) {
                int o = w*4 + oo;
                ob[(size_t)o*HW + lane] = fmaf(xts[o*33 + lane], sc4[oo], bi4[oo]);
            }
        }
    }
}

// ---------------- launch ----------------
extern "C" void kernel_launch(void* const* d_in, const int* in_sizes, int n_in,
                              void* d_out, int out_size) {
    const float* x     = (const float*)d_in[0];
    const int*   index = (const int*)  d_in[1];
    const float* Wft   = (const float*)d_in[2];
    const float* Wm    = (const float*)d_in[3];
    const float* gamma = (const float*)d_in[4];
    const float* beta  = (const float*)d_in[5];
    float* out = (float*)d_out;

    cudaFuncSetAttribute(k_all, cudaFuncAttributeMaxDynamicSharedMemorySize, SMEM_BYTES);
    k_all<<<GRIDN, NT, SMEM_BYTES>>>(x, Wft, index, Wm, out, gamma, beta);
}

// round 10
// speedup vs baseline: 1.1020x; 1.0214x over previous
#include <cuda_runtime.h>

#define HW   16384
#define NB   2
#define CIN  128
#define CO   64
#define NK   64
#define NPIX (NB*HW)
#define GRIDN 129u
#define NT    512

// accumulator pack
#define ACC_SUMS  0        // 8192 floats: [b][k][o]
#define ACC_CNT   8192     // 128 floats:  [b][k]
#define ACC_BNSUM 8320     // 64
#define ACC_BNSQ  8384     // 64
#define ACCN      8448

// smem layout (floats)
// GEMM: ws[8192] | xs[2h x 2buf x 2048 = 8192] | scnt[64] | sidx[256 ints]
#define XS_OFF    8192
#define SCNT_OFF  16384
#define SIDX_OFF  16448
#define FEAT_OFF  16704
#define FEAT_STR  68                      // 64 ch + 4 pad per px
#define SMEM_FLOATS (FEAT_OFF + 256*FEAT_STR)   // 34112
#define SMEM_BYTES  (SMEM_FLOATS*4)             // 136448

// ---------------- scratch (static device globals; zero-initialized by loader) ----------------
__device__ float    g_acc[ACCN];
__device__ unsigned g_bar;                   // monotonic ticket barrier
__device__ float    g_invcov[CO*CO];
__device__ float    g_means[NB*NK*CO];
__device__ float    g_T[NB*NK*CO];
__device__ float    g_diag[NB*NK];
__device__ float    g_adjm[NB*NK*CO];

// ---------------- helpers ----------------
__device__ __forceinline__ unsigned long long pk2(float v) {
    unsigned long long r; unsigned u = __float_as_uint(v);
    asm("mov.b64 %0, {%1, %2};" : "=l"(r) : "r"(u), "r"(u));
    return r;
}
__device__ __forceinline__ void ffma2(unsigned long long& d,
                                      unsigned long long a, unsigned long long b) {
    asm("fma.rn.f32x2 %0, %1, %2, %3;" : "=l"(d) : "l"(a), "l"(b), "l"(d));
}
__device__ __forceinline__ void red4(float* p, float a, float b, float c, float d) {
    asm volatile("red.add.v4.f32 [%0], {%1, %2, %3, %4};"
                 :: "l"(p), "f"(a), "f"(b), "f"(c), "f"(d) : "memory");
}
__device__ __forceinline__ void cpa16(float* sdst, const float* gsrc) {
    unsigned saddr = (unsigned)__cvta_generic_to_shared(sdst);
    asm volatile("cp.async.ca.shared.global [%0], [%1], 16;" :: "r"(saddr), "l"(gsrc));
}
__device__ __forceinline__ void cpa_commit() { asm volatile("cp.async.commit_group;"); }
template<int N> __device__ __forceinline__ void cpa_wait() {
    asm volatile("cp.async.wait_group %0;" :: "n"(N));
}

// device-wide ticket barrier; all GRIDN blocks resident, monotonic across replays
__device__ __forceinline__ void gbar() {
    __threadfence();
    __syncthreads();
    if (threadIdx.x == 0) {
        unsigned t   = atomicAdd(&g_bar, 1u);
        unsigned tgt = (t / GRIDN + 1u) * GRIDN;
        unsigned v;
        for (;;) {
            asm volatile("ld.acquire.gpu.u32 %0, [%1];" : "=r"(v) : "l"(&g_bar) : "memory");
            if (v >= tgt) break;
            __nanosleep(32);
        }
    }
    __syncthreads();
}

// ---------------- the single fused kernel ----------------
__global__ __launch_bounds__(NT) void k_all(const float* __restrict__ x,
                                            const float* __restrict__ Wft,
                                            const int*   __restrict__ idx,
                                            const float* __restrict__ Wm,
                                            float* __restrict__ out,
                                            const float* __restrict__ gamma,
                                            const float* __restrict__ beta) {
    extern __shared__ float sm[];
    int*   sidxP = (int*)(sm + SIDX_OFF);
    float* feat  = sm + FEAT_OFF;
    const int tid = threadIdx.x;
    const int bx  = blockIdx.x;

    const int P0  = bx * 256;                  // pixel tile for blocks 0..127
    const int b   = P0 >> 14;
    const int hw0 = P0 & (HW-1);

    // ================= P0: split-K GEMM (0..127) | inverse (128) =================
    if (bx == 128) {
        if (tid < 128) g_acc[ACC_BNSUM + tid] = 0.f;
        float* aug  = sm;            // 64 x 128
        float* colp = sm + 8192;     // 64
        float* prow = sm + 8256;     // 128
        for (int e = tid; e < 4096; e += NT) {
            int i = e >> 6, j = e & 63;
            float s = 0.f;
            for (int c = 0; c < 64; c += 4) {
                float4 a  = *(const float4*)(Wm + i*64 + c);
                float4 bb = *(const float4*)(Wm + j*64 + c);
                s += a.x*bb.x + a.y*bb.y + a.z*bb.z + a.w*bb.w;
            }
            aug[i*128 + j]      = s;
            aug[i*128 + 64 + j] = (i == j) ? 1.f : 0.f;
        }
        __syncthreads();
        for (int p = 0; p < 64; p++) {
            if (tid < 64) {
                colp[tid] = aug[tid*128 + p];
            } else if (tid < 192) {
                int j = tid - 64;
                prow[j] = aug[p*128 + j] * (1.f / aug[p*128 + p]);
            }
            __syncthreads();
            for (int e = tid; e < 8192; e += NT) {
                int i = e >> 7, j = e & 127;
                float pr = prow[j];
                aug[e] = (i == p) ? pr : fmaf(-colp[i], pr, aug[e]);
            }
            __syncthreads();
        }
        for (int e = tid; e < 4096; e += NT)
            g_invcov[e] = aug[(e>>6)*128 + 64 + (e&63)];
    } else {
        // ---- GEMM: 256 px x 64 o, split-K halves (64 ch each), 8px x 8o per thread ----
        float* ws   = sm;                 // 8192 = full Wft [ch][64]
        float* xs   = sm + XS_OFF;        // [h][buf][8ch][256px]
        float* scnt = sm + SCNT_OFF;      // 64

        const float* xb = x + (size_t)b*CIN*HW + hw0;

        if (tid < 64) {
            scnt[tid] = 0.f;
            ((int4*)sidxP)[tid] = ((const int4*)(idx + P0))[tid];
        }

        const int h    = tid >> 8;        // K-half: 0 -> ch 0..63, 1 -> ch 64..127
        const int htid = tid & 255;
        const int chg  = htid & 7;        // 8 o-groups of 8
        const int pxg  = htid >> 3;       // 32 px-groups: px {pxg*4..+3} U {128+pxg*4..+3}
        unsigned long long acc2[8][4];
#pragma unroll
        for (int i = 0; i < 8; i++)
#pragma unroll
            for (int j = 0; j < 4; j++) acc2[i][j] = 0ull;

        // stage whole Wft + both halves' tile 0
        for (int e = tid; e < 2048; e += NT)
            cpa16(ws + e*4, Wft + e*4);
#pragma unroll
        for (int k = 0; k < 2; k++) {
            int e   = tid + k*NT;                 // 0..1023
            int hh  = e >> 9, row = (e >> 6) & 7, col = (e & 63) * 4;
            cpa16(xs + ((hh*2 + 0)*8 + row)*256 + col,
                  xb + (size_t)(hh*64 + row)*HW + col);
        }
        cpa_commit();

        for (int t = 0; t < 8; t++) {             // 8 tiles of 8 channels per half
            const int buf = t & 1;
            if (t < 7) {
#pragma unroll
                for (int k = 0; k < 2; k++) {
                    int e   = tid + k*NT;
                    int hh  = e >> 9, row = (e >> 6) & 7, col = (e & 63) * 4;
                    cpa16(xs + ((hh*2 + (buf^1))*8 + row)*256 + col,
                          xb + (size_t)(hh*64 + (t+1)*8 + row)*HW + col);
                }
                cpa_commit();
                cpa_wait<1>();
            } else {
                cpa_wait<0>();
            }
            __syncthreads();
            const float* xsb = xs + (h*2 + buf)*2048;
            const float* wsh = ws + h*4096 + t*512;
#pragma unroll
            for (int cc = 0; cc < 8; cc++) {
                float xv[8];
                *(float4*)(xv)   = *(const float4*)(xsb + cc*256 + pxg*4);
                *(float4*)(xv+4) = *(const float4*)(xsb + cc*256 + 128 + pxg*4);
                ulonglong2 wA = *(const ulonglong2*)(wsh + cc*64 + chg*8);
                ulonglong2 wB = *(const ulonglong2*)(wsh + cc*64 + chg*8 + 4);
#pragma unroll
                for (int i = 0; i < 8; i++) {
                    unsigned long long ax = pk2(xv[i]);
                    ffma2(acc2[i][0], ax, wA.x);
                    ffma2(acc2[i][1], ax, wA.y);
                    ffma2(acc2[i][2], ax, wB.x);
                    ffma2(acc2[i][3], ax, wB.y);
                }
            }
            __syncthreads();
        }

        // ---- epilogue: reduce K-halves directly into smem feat + global segment sums ----
#pragma unroll
        for (int i = 0; i < 8; i++) {
            int px = (i < 4) ? (pxg*4 + i) : (128 + pxg*4 + (i - 4));
            unsigned long long a0 = acc2[i][0], a1 = acc2[i][1],
                               a2 = acc2[i][2], a3 = acc2[i][3];
            float v0 = __uint_as_float((unsigned)a0), v1 = __uint_as_float((unsigned)(a0>>32));
            float v2 = __uint_as_float((unsigned)a1), v3 = __uint_as_float((unsigned)(a1>>32));
            float v4 = __uint_as_float((unsigned)a2), v5 = __uint_as_float((unsigned)(a2>>32));
            float v6 = __uint_as_float((unsigned)a3), v7 = __uint_as_float((unsigned)(a3>>32));
            if (h == 0) {
                *(float4*)(feat + px*FEAT_STR + chg*8)     = make_float4(v0,v1,v2,v3);
                *(float4*)(feat + px*FEAT_STR + chg*8 + 4) = make_float4(v4,v5,v6,v7);
            } else {
                acc2[i][0] = a0; // keep in regs; added after sync below
            }
        }
        __syncthreads();
        if (h == 1) {
#pragma unroll
            for (int i = 0; i < 8; i++) {
                int px = (i < 4) ? (pxg*4 + i) : (128 + pxg*4 + (i - 4));
                unsigned long long a0 = acc2[i][0], a1 = acc2[i][1],
                                   a2 = acc2[i][2], a3 = acc2[i][3];
                float4 p0 = *(float4*)(feat + px*FEAT_STR + chg*8);
                float4 p1 = *(float4*)(feat + px*FEAT_STR + chg*8 + 4);
                float v0 = p0.x + __uint_as_float((unsigned)a0);
                float v1 = p0.y + __uint_as_float((unsigned)(a0>>32));
                float v2 = p0.z + __uint_as_float((unsigned)a1);
                float v3 = p0.w + __uint_as_float((unsigned)(a1>>32));
                float v4 = p1.x + __uint_as_float((unsigned)a2);
                float v5 = p1.y + __uint_as_float((unsigned)(a2>>32));
                float v6 = p1.z + __uint_as_float((unsigned)a3);
                float v7 = p1.w + __uint_as_float((unsigned)(a3>>32));
                *(float4*)(feat + px*FEAT_STR + chg*8)     = make_float4(v0,v1,v2,v3);
                *(float4*)(feat + px*FEAT_STR + chg*8 + 4) = make_float4(v4,v5,v6,v7);
                int k = sidxP[px];
                float* sp = g_acc + ACC_SUMS + ((b*NK + k)*CO + chg*8);
                red4(sp,     v0,v1,v2,v3);
                red4(sp + 4, v4,v5,v6,v7);
                if (chg == 0) atomicAdd(&scnt[k], 1.f);
            }
        }
        __syncthreads();
        if (tid < 64) atomicAdd(&g_acc[ACC_CNT + b*64 + tid], scnt[tid]);
    }
    gbar();

    // ================= P1: adjA (blocks 0..15) =================
    if (bx < 16) {
        float* As = sm;            // 4096
        float* mR = sm + 4096;     // 512
        float* tR = sm + 4608;     // 512
        const int ab = bx >> 3, r0 = (bx & 7) * 8;
        for (int e4 = tid; e4 < 1024; e4 += NT)
            ((float4*)As)[e4] = ((const float4*)g_invcov)[e4];
        for (int e = tid; e < 512; e += NT) {
            int rl = e >> 6;
            float c = g_acc[ACC_CNT + ab*64 + r0 + rl];
            float v = g_acc[ACC_SUMS + ab*4096 + r0*64 + e] / ((c > 0.f) ? c : 1.f);
            mR[e] = v;
            g_means[ab*4096 + r0*64 + e] = v;
        }
        __syncthreads();
        {
            int il = tid >> 6, j = tid & 63;
            float a = 0.f;
            for (int c = 0; c < 64; c++)
                a = fmaf(mR[il*64 + c], As[c*64 + j], a);
            tR[il*64 + j] = a;
            g_T[ab*4096 + (r0+il)*64 + j] = a;
        }
        __syncthreads();
        if (tid < 8) {
            float d = 0.f;
            for (int c = 0; c < 64; c++)
                d = fmaf(tR[tid*64 + c], mR[tid*64 + c], d);
            g_diag[ab*64 + r0 + tid] = d;
        }
    }
    gbar();

    // ================= P2: adjB (blocks 0..15) =================
    if (bx < 16) {
        float* Ms   = sm;          // 4096 swizzled means [c*64 + (j^(c&31))]
        float* tRb  = sm + 4096;   // 512
        float* sadj = sm + 4608;   // 512
        float* dg   = sm + 5120;   // 64
        const int ab = bx >> 3, r0 = (bx & 7) * 8;
        for (int e = tid; e < 4096; e += NT) {
            int j = e >> 6, c = e & 63;
            Ms[c*64 + (j ^ (c & 31))] = g_means[ab*4096 + e];
        }
        for (int e = tid; e < 512; e += NT)
            tRb[e] = g_T[ab*4096 + r0*64 + e];
        if (tid < 64) dg[tid] = g_diag[ab*64 + tid];
        __syncthreads();
        {
            int il = tid >> 6, j = tid & 63;
            float a = 0.f;
            for (int c = 0; c < 64; c++)
                a = fmaf(tRb[il*64 + c], Ms[c*64 + (j ^ (c & 31))], a);
            float q = dg[r0+il] + dg[j] - 2.f*a;
            sadj[il*64 + j] = expf(-sqrtf(fmaxf(q, 1e-12f)));
        }
        __syncthreads();
        {
            int il = tid >> 6, o = tid & 63;
            float a = 0.f;
            for (int jj = 0; jj < 64; jj++)
                a = fmaf(sadj[il*64 + jj], Ms[o*64 + (jj ^ (o & 31))], a);
            g_adjm[ab*4096 + (r0+il)*64 + o] = a;
        }
    }
    gbar();

    // ================= P3: features in smem + BN stats (blocks 0..127) =================
    if (bx < 128) {
        float* am4 = sm;           // 4096
        float* red = sm + 4096;    // 4096: s partials [2048] + q partials [2048]
        for (int e4 = tid; e4 < 1024; e4 += NT)
            ((float4*)am4)[e4] = ((const float4*)(g_adjm + b*4096))[e4];
        if (tid < 65) g_acc[bx*65 + tid] = 0.f;     // re-zero SUMS+CNT for next replay
        __syncthreads();

        const int pr = tid >> 4, c4 = tid & 15;     // 32 px-rows x 16 ch-chunks
        float4 s4 = make_float4(0,0,0,0), q4 = make_float4(0,0,0,0);
#pragma unroll
        for (int it = 0; it < 8; it++) {
            int px = it*32 + pr;
            int k  = sidxP[px];
            float4* fp = (float4*)(feat + px*FEAT_STR + c4*4);
            float4 xv = *fp;
            float4 av = ((float4*)am4)[k*16 + c4];
            float v0 = fmaxf(xv.x+av.x, 0.f), v1 = fmaxf(xv.y+av.y, 0.f);
            float v2 = fmaxf(xv.z+av.z, 0.f), v3 = fmaxf(xv.w+av.w, 0.f);
            *fp = make_float4(v0, v1, v2, v3);      // features materialized in smem
            s4.x += v0; s4.y += v1; s4.z += v2; s4.w += v3;
            q4.x += v0*v0; q4.y += v1*v1; q4.z += v2*v2; q4.w += v3*v3;
        }
        ((float4*)red)[pr*16 + c4] = s4;
        ((float4*)(red + 2048))[pr*16 + c4] = q4;
        __syncthreads();
        if (tid < 64) {
            float s = 0.f, q = 0.f;
#pragma unroll
            for (int p = 0; p < 32; p++) { s += red[p*64 + tid]; q += red[2048 + p*64 + tid]; }
            atomicAdd(&g_acc[ACC_BNSUM + tid], s);
            atomicAdd(&g_acc[ACC_BNSQ  + tid], q);
        }
    }
    gbar();

    // ================= P4: normalize from smem features, coalesced write =================
    if (bx < 128) {
        float* xts = sm;           // 2112  [o][px] padded 33
        float* ssc = sm + 2112;    // 64
        float* sbi = sm + 2176;    // 64
        if (tid < 64) {
            const float invN = 1.f/(float)NPIX;
            float mean = __ldcg(&g_acc[ACC_BNSUM + tid])*invN;
            float var  = __ldcg(&g_acc[ACC_BNSQ  + tid])*invN - mean*mean;
            float s = gamma[tid]*rsqrtf(var + 1e-5f);
            ssc[tid] = s; sbi[tid] = beta[tid] - mean*s;
        }
        __syncthreads();

        const int w = tid >> 5, lane = tid & 31;    // 16 warps x 4 o each
        float sc4[4], bi4[4];
#pragma unroll
        for (int oo = 0; oo < 4; oo++) { sc4[oo] = ssc[w*4+oo]; bi4[oo] = sbi[w*4+oo]; }

        for (int st = 0; st < 8; st++) {            // 8 subtiles of 32 px
            __syncthreads();
            for (int e4 = tid; e4 < 512; e4 += NT) {
                int flat = e4*4, pxl = flat >> 6, o = flat & 63;
                float4 v = *(const float4*)(feat + (st*32 + pxl)*FEAT_STR + o);
                xts[(o+0)*33 + pxl] = v.x;
                xts[(o+1)*33 + pxl] = v.y;
                xts[(o+2)*33 + pxl] = v.z;
                xts[(o+3)*33 + pxl] = v.w;
            }
            __syncthreads();
            float* ob = out + (size_t)b*CO*HW + hw0 + st*32;
#pragma unroll
            for (int oo = 0; oo < 4; oo++) {
                int o = w*4 + oo;
                ob[(size_t)o*HW + lane] = fmaf(xts[o*33 + lane], sc4[oo], bi4[oo]);
            }
        }
    }
}

// ---------------- launch ----------------
extern "C" void kernel_launch(void* const* d_in, const int* in_sizes, int n_in,
                              void* d_out, int out_size) {
    const float* x     = (const float*)d_in[0];
    const int*   index = (const int*)  d_in[1];
    const float* Wft   = (const float*)d_in[2];
    const float* Wm    = (const float*)d_in[3];
    const float* gamma = (const float*)d_in[4];
    const float* beta  = (const float*)d_in[5];
    float* out = (float*)d_out;

    cudaFuncSetAttribute(k_all, cudaFuncAttributeMaxDynamicSharedMemorySize, SMEM_BYTES);
    k_all<<<GRIDN, NT, SMEM_BYTES>>>(x, Wft, index, Wm, out, gamma, beta);
}